// round 11
// baseline (speedup 1.0000x reference)
#include <cuda_runtime.h>
#include <cstdint>

#define B_   2
#define C_   32
#define T_   64
#define HW_  4096
#define N_   512
#define BN_  (B_*N_)         /* 1024 */
#define CH_  16
#define FT_  400
#define L_   (FT_*N_)        /* 204800 */
#define CNT_ (B_*L_)         /* 409600 */
#define OUT_OFF_RESULT ((size_t)B_*CH_*L_)  /* 6,553,600 */

// ---- scratch (device globals) ----
__device__ __align__(16) float g_r[B_*T_*HW_];            // 2 MB
// g_f: quad-plane layout. float4 plane p = t*4 + q, index [p][bn]
__device__ __align__(16) float g_f[(size_t)T_*4*BN_*4];   // 4 MB
__device__ __align__(16) float g_part[32*BN_];            // [col][bn]
__device__ float g_ss[32];                                // sums[16] + sumsqs[16]
__device__ unsigned g_count = 0;

// ---- cp.async helpers ----
__device__ __forceinline__ void cp_async16(uint32_t dst, const void* src) {
    asm volatile("cp.async.ca.shared.global [%0], [%1], 16;" :: "r"(dst), "l"(src));
}
__device__ __forceinline__ void cp_commit() {
    asm volatile("cp.async.commit_group;");
}
template<int NN> __device__ __forceinline__ void cp_wait() {
    asm volatile("cp.async.wait_group %0;" :: "n"(NN));
}

// ---- compile-time lerp stat tables (fp32 ops identical to reference) ----
struct LerpTab { float wl[64]; float A[64]; float Bc[64]; float Cc[64]; };
constexpr LerpTab make_tab() {
    LerpTab tb{};
    const float step = (float)(63.0/399.0);
    for (int t = 0; t < FT_; t++) {
        float pos = (float)t * step;
        int i0 = (int)pos;
        int i1 = (i0 + 1 < T_) ? i0 + 1 : T_ - 1;
        float w = pos - (float)i0;
        float w0 = 1.0f - w;
        if (i1 == i0) {
            tb.wl[i0] += (w0 + w);
            tb.A[i0]  += (w0 + w) * (w0 + w);
        } else {
            tb.wl[i0] += w0;  tb.wl[i1] += w;
            tb.A[i0]  += w0 * w0;
            tb.Bc[i0] += 2.0f * w0 * w;
            tb.Cc[i0] += w * w;
        }
    }
    return tb;
}
__constant__ LerpTab c_tab = make_tab();

// ============================================================================
// k_main: blocks [0,1024) gather path (= round-7 champion code);
//         blocks [1024,2048) r path with cp.async 8ch x 4-stage ring (33 KB).
// ============================================================================
__global__ void __launch_bounds__(128, 6) k_main(
    const float* __restrict__ x, const int* __restrict__ coord,
    const float* __restrict__ Wr, const float* __restrict__ br,
    const float* __restrict__ W1, const float* __restrict__ Wf,
    const float* __restrict__ b1, const float* __restrict__ bf)
{
    // one 33 KB arena aliased by both paths
    __shared__ __align__(16) float sm[8224];
    __shared__ unsigned s_last;

    int bid = blockIdx.x;
    int tid = threadIdx.x;

    if (bid >= 1024) {
        // ---- r path: cp.async ring, 4 stages of 8 channels ----
        float (*buf)[8][512] = (float (*)[8][512])sm;   // 2 buffers x 8ch x 512
        float* w = sm + 8192;                            // Wr[32]
        if (tid < 32) w[tid] = Wr[tid];
        __syncthreads();

        int rb = bid - 1024;
        int chunk = rb & 7;
        int bt = rb >> 3;
        int b = bt >> 6, t = bt & 63;
        int col = tid * 4;
        const float* base = x + ((size_t)(b*C_)*T_ + t)*HW_ + chunk*512 + col;
        uint32_t s0 = (uint32_t)__cvta_generic_to_shared(&buf[0][0][col]);
        uint32_t s1 = (uint32_t)__cvta_generic_to_shared(&buf[1][0][col]);

        // issue stage 0 (ch 0-7) -> buf0, stage 1 (ch 8-15) -> buf1
        #pragma unroll
        for (int c = 0; c < 8; c++)
            cp_async16(s0 + c*2048, base + (size_t)c*T_*HW_);
        cp_commit();
        #pragma unroll
        for (int c = 0; c < 8; c++)
            cp_async16(s1 + c*2048, base + (size_t)(8+c)*T_*HW_);
        cp_commit();

        float brv = br[0];
        float4 acc = make_float4(brv, brv, brv, brv);

        // consume stage 0, issue stage 2 (ch 16-23) -> buf0
        cp_wait<1>();
        #pragma unroll
        for (int c = 0; c < 8; c++) {
            float4 v = *(const float4*)&buf[0][c][col];
            float wc = w[c];
            acc.x += wc*v.x; acc.y += wc*v.y; acc.z += wc*v.z; acc.w += wc*v.w;
        }
        #pragma unroll
        for (int c = 0; c < 8; c++)
            cp_async16(s0 + c*2048, base + (size_t)(16+c)*T_*HW_);
        cp_commit();

        // consume stage 1, issue stage 3 (ch 24-31) -> buf1
        cp_wait<1>();
        #pragma unroll
        for (int c = 0; c < 8; c++) {
            float4 v = *(const float4*)&buf[1][c][col];
            float wc = w[8+c];
            acc.x += wc*v.x; acc.y += wc*v.y; acc.z += wc*v.z; acc.w += wc*v.w;
        }
        #pragma unroll
        for (int c = 0; c < 8; c++)
            cp_async16(s1 + c*2048, base + (size_t)(24+c)*T_*HW_);
        cp_commit();

        cp_wait<1>();
        #pragma unroll
        for (int c = 0; c < 8; c++) {
            float4 v = *(const float4*)&buf[0][c][col];
            float wc = w[16+c];
            acc.x += wc*v.x; acc.y += wc*v.y; acc.z += wc*v.z; acc.w += wc*v.w;
        }
        cp_wait<0>();
        #pragma unroll
        for (int c = 0; c < 8; c++) {
            float4 v = *(const float4*)&buf[1][c][col];
            float wc = w[24+c];
            acc.x += wc*v.x; acc.y += wc*v.y; acc.z += wc*v.z; acc.w += wc*v.w;
        }
        *(float4*)&g_r[(size_t)bt*HW_ + chunk*512 + col] = acc;
        return;
    }

    // ---- gather path (round-7 champion code, smem aliased into sm) ----
    float* xg    = sm;           // 2048: x [c][t] / Wf stage
    float* sf    = sm + 2048;    // 1024: f [t][o] / W1 stage
    float* sWt   = sm + 3072;    // 512:  folded [c][o]
    float* sbe   = sm + 3584;    // 16
    float* sbf   = sm + 3600;    // 32
    float* red_s = sm + 3648;    // 128
    float* red_q = sm + 3776;    // 128

    int bn = bid;                          // 0..1023
    int b = bn >> 9;
    int idx = coord[bn*2]*64 + coord[bn*2+1];

    // issue 16 scattered x loads early (max MLP)
    const float* xp = x + (size_t)b*C_*T_*HW_ + idx;
    float rv[16];
    #pragma unroll
    for (int i = 0; i < 16; i++)
        rv[i] = xp[(size_t)(tid + i*128) * HW_];

    // stage W1 -> sf, Wf -> xg, bf -> sbf
    for (int e = tid; e < CH_*C_; e += 128) sf[e] = W1[e];
    for (int e = tid; e < C_*C_; e += 128) xg[e] = Wf[e];
    if (tid < 32) sbf[tid] = bf[tid];
    __syncthreads();

    // fold: sWt[c][o] = sum_k W1[o][k] * Wf[k][c]
    #pragma unroll
    for (int i = 0; i < 4; i++) {
        int e = tid*4 + i;
        int c = e >> 4, o = e & 15;
        float a = 0.f;
        #pragma unroll
        for (int k = 0; k < 32; k++) a += sf[o*32+k] * xg[k*32 + c];
        sWt[c*CH_+o] = a;
    }
    if (tid < CH_) {
        float bb = b1[tid];
        #pragma unroll
        for (int k = 0; k < 32; k++) bb += sf[tid*32+k] * sbf[k];
        sbe[tid] = bb;
    }
    __syncthreads();
    #pragma unroll
    for (int i = 0; i < 16; i++) xg[tid + i*128] = rv[i];   // park x [c][t]
    __syncthreads();

    // f[t][o] = beff[o] + sum_c Wt[c][o] * xg[c][t]
    #pragma unroll
    for (int i = 0; i < 8; i++) {
        int e = tid + i*128;
        int t = e >> 4, o = e & 15;
        float a = sbe[o];
        #pragma unroll
        for (int c = 0; c < 32; c++) a += sWt[c*CH_+o] * xg[c*64+t];
        sf[e] = a;
    }
    __syncthreads();

    // store f -> g_f quad-plane layout: plane p = t*4+q, slot bn
    {
        float4* gf4 = (float4*)g_f;
        const float4* sf4 = (const float4*)sf;
        #pragma unroll
        for (int i = 0; i < 2; i++) {
            int e4 = tid + i*128;            // e4 = t*4 + q
            gf4[(size_t)e4*BN_ + bn] = sf4[e4];
        }
    }

    // table-based stats
    {
        int o = tid & 15, j = tid >> 4;
        float s_acc = 0.f, q_acc = 0.f;
        #pragma unroll
        for (int k = 0; k < 8; k++) {
            int i  = j + k*8;
            int i1 = (i < 63) ? i + 1 : 63;
            float fi  = sf[i*16 + o];
            float fi1 = sf[i1*16 + o];
            s_acc += c_tab.wl[i] * fi;
            q_acc += c_tab.A[i]*fi*fi + c_tab.Bc[i]*fi*fi1 + c_tab.Cc[i]*fi1*fi1;
        }
        red_s[j*16 + o] = s_acc;
        red_q[j*16 + o] = q_acc;
    }
    __syncthreads();
    if (tid < 32) {
        int c = tid & 15;
        const float* src = (tid < 16) ? red_s : red_q;
        float tot = 0.f;
        #pragma unroll
        for (int jj = 0; jj < 8; jj++) tot += src[jj*16 + c];
        g_part[tid*BN_ + bn] = tot;
    }

    // last gather block folds g_part -> g_ss
    __threadfence();
    if (tid == 0) s_last = (atomicAdd(&g_count, 1u) == 1023u) ? 1u : 0u;
    __syncthreads();
    if (s_last) {
        int c = tid >> 2, qd = tid & 3;
        const float4* p = (const float4*)(g_part + c*BN_) + qd*64;
        float acc = 0.f;
        #pragma unroll 16
        for (int k = 0; k < 64; k++) {
            float4 v4 = p[k];
            acc += (v4.x + v4.y) + (v4.z + v4.w);
        }
        red_s[tid] = acc;
        __syncthreads();
        if (tid < 32) {
            g_ss[tid] = (red_s[tid*4] + red_s[tid*4+1])
                      + (red_s[tid*4+2] + red_s[tid*4+3]);
            if (tid == 0) g_count = 0;   // reset for next graph replay
        }
    }
}

// ============================================================================
// k_fin: blocks [0,3200) -> result lerp; blocks [3200,4800) -> BN+ReLU+W2
// (byte-identical to the 65.2 champion)
// ============================================================================
__global__ void __launch_bounds__(256) k_fin(
    const float* __restrict__ gamma, const float* __restrict__ beta,
    const float* __restrict__ W2, const float* __restrict__ b2,
    float* __restrict__ out)
{
    __shared__ float sW2[CH_*CH_], sb2[CH_], ssc[CH_], ssh[CH_];

    if (blockIdx.x < 3200) {
        int tid = blockIdx.x*256 + threadIdx.x;      // 819200
        int hw4 = tid & 1023;
        int bt  = tid >> 10;
        int t = bt % FT_;
        int b = bt / FT_;
        const float step = (float)(63.0/399.0);
        float pos = (float)t * step;
        int i0 = (int)pos;
        int i1 = min(i0+1, T_-1);
        float w = pos - (float)i0, w0 = 1.f - w;
        float4 a = ((const float4*)(g_r + (b*T_+i0)*HW_))[hw4];
        float4 c = ((const float4*)(g_r + (b*T_+i1)*HW_))[hw4];
        float4 v = make_float4(a.x*w0 + c.x*w, a.y*w0 + c.y*w,
                               a.z*w0 + c.z*w, a.w*w0 + c.w*w);
        ((float4*)(out + OUT_OFF_RESULT))[tid] = v;
        return;
    }

    if (threadIdx.x < CH_*CH_) sW2[threadIdx.x] = W2[threadIdx.x];
    if (threadIdx.x < CH_) {
        int o = threadIdx.x;
        sb2[o] = b2[o];
        float mean = g_ss[o]    * (1.f/(float)CNT_);
        float var  = g_ss[o+16] * (1.f/(float)CNT_) - mean*mean;
        float sc = gamma[o] * rsqrtf(var + 1e-5f);
        ssc[o] = sc;
        ssh[o] = beta[o] - mean*sc;
    }
    __syncthreads();
    int tid = (blockIdx.x - 3200)*256 + threadIdx.x;  // 409600
    int b = tid / L_;
    int l = tid - b*L_;
    int t = l >> 9, n = l & (N_-1);
    int bn = b*N_ + n;
    const float step = (float)(63.0/399.0);
    float pos = (float)t * step;
    int i0 = (int)pos;
    int i1 = min(i0+1, T_-1);
    float w = pos - (float)i0, w0 = 1.f - w;
    const float4* gf4 = (const float4*)g_f;
    float4 a0 = gf4[(size_t)(i0*4+0)*BN_ + bn];
    float4 a1 = gf4[(size_t)(i0*4+1)*BN_ + bn];
    float4 a2 = gf4[(size_t)(i0*4+2)*BN_ + bn];
    float4 a3 = gf4[(size_t)(i0*4+3)*BN_ + bn];
    float4 c0 = gf4[(size_t)(i1*4+0)*BN_ + bn];
    float4 c1 = gf4[(size_t)(i1*4+1)*BN_ + bn];
    float4 c2 = gf4[(size_t)(i1*4+2)*BN_ + bn];
    float4 c3 = gf4[(size_t)(i1*4+3)*BN_ + bn];
    float hr[CH_];
    hr[0]=a0.x*w0+c0.x*w; hr[1]=a0.y*w0+c0.y*w; hr[2]=a0.z*w0+c0.z*w; hr[3]=a0.w*w0+c0.w*w;
    hr[4]=a1.x*w0+c1.x*w; hr[5]=a1.y*w0+c1.y*w; hr[6]=a1.z*w0+c1.z*w; hr[7]=a1.w*w0+c1.w*w;
    hr[8]=a2.x*w0+c2.x*w; hr[9]=a2.y*w0+c2.y*w; hr[10]=a2.z*w0+c2.z*w; hr[11]=a2.w*w0+c2.w*w;
    hr[12]=a3.x*w0+c3.x*w; hr[13]=a3.y*w0+c3.y*w; hr[14]=a3.z*w0+c3.z*w; hr[15]=a3.w*w0+c3.w*w;
    #pragma unroll
    for (int o = 0; o < CH_; o++) hr[o] = fmaxf(ssc[o]*hr[o] + ssh[o], 0.f);
    #pragma unroll
    for (int o2 = 0; o2 < CH_; o2++) {
        float acc = sb2[o2];
        #pragma unroll
        for (int o = 0; o < CH_; o++) acc += sW2[o2*16+o] * hr[o];
        out[((size_t)(b*CH_+o2))*L_ + l] = acc;
    }
}

extern "C" void kernel_launch(void* const* d_in, const int* in_sizes, int n_in,
                              void* d_out, int out_size) {
    const float* x     = (const float*)d_in[0];
    const int*   coord = (const int*)  d_in[1];
    const float* Wf    = (const float*)d_in[2];
    const float* bf    = (const float*)d_in[3];
    const float* Wr    = (const float*)d_in[4];
    const float* br    = (const float*)d_in[5];
    const float* W1    = (const float*)d_in[6];
    const float* b1    = (const float*)d_in[7];
    const float* gamma = (const float*)d_in[8];
    const float* beta  = (const float*)d_in[9];
    const float* W2    = (const float*)d_in[10];
    const float* b2    = (const float*)d_in[11];
    float* out = (float*)d_out;

    k_main<<<2048, 128>>>(x, coord, Wr, br, W1, Wf, b1, bf);
    k_fin <<<4800, 256>>>(gamma, beta, W2, b2, out);
}

// round 12
// speedup vs baseline: 1.2033x; 1.2033x over previous
#include <cuda_runtime.h>
#include <cstdint>

#define B_   2
#define C_   32
#define T_   64
#define HW_  4096
#define N_   512
#define BN_  (B_*N_)         /* 1024 */
#define CH_  16
#define FT_  400
#define L_   (FT_*N_)        /* 204800 */
#define CNT_ (B_*L_)         /* 409600 */
#define OUT_OFF_RESULT ((size_t)B_*CH_*L_)  /* 6,553,600 */

// ---- scratch (device globals) ----
__device__ __align__(16) float g_r[B_*T_*HW_];            // 2 MB
// g_f: quad-plane layout. float4 plane p = t*4 + q, index [p][bn]
__device__ __align__(16) float g_f[(size_t)T_*4*BN_*4];   // 4 MB
__device__ __align__(16) float g_part[32*BN_];            // [col][bn]
__device__ float g_ss[32];                                // sums[16] + sumsqs[16]
__device__ unsigned g_count = 0;

// ---- compile-time lerp stat tables (fp32 ops identical to reference) ----
struct LerpTab { float wl[64]; float A[64]; float Bc[64]; float Cc[64]; };
constexpr LerpTab make_tab() {
    LerpTab tb{};
    const float step = (float)(63.0/399.0);
    for (int t = 0; t < FT_; t++) {
        float pos = (float)t * step;
        int i0 = (int)pos;
        int i1 = (i0 + 1 < T_) ? i0 + 1 : T_ - 1;
        float w = pos - (float)i0;
        float w0 = 1.0f - w;
        if (i1 == i0) {
            tb.wl[i0] += (w0 + w);
            tb.A[i0]  += (w0 + w) * (w0 + w);
        } else {
            tb.wl[i0] += w0;  tb.wl[i1] += w;
            tb.A[i0]  += w0 * w0;
            tb.Bc[i0] += 2.0f * w0 * w;
            tb.Cc[i0] += w * w;
        }
    }
    return tb;
}
__constant__ LerpTab c_tab = make_tab();

// ============================================================================
// k_main: even blocks -> gather path; odd blocks -> r stream path (interleaved
// so every wave carries a 50/50 mix of stream + scattered traffic).
// Last gather block folds g_part -> g_ss (BN stats).
// ============================================================================
__global__ void __launch_bounds__(128, 8) k_main(
    const float* __restrict__ x, const int* __restrict__ coord,
    const float* __restrict__ Wr, const float* __restrict__ br,
    const float* __restrict__ W1, const float* __restrict__ Wf,
    const float* __restrict__ b1, const float* __restrict__ bf)
{
    __shared__ float xg[C_*T_];      // gather x [c][t] / Wf stage / r: Wr
    __shared__ float sWt[C_*CH_];    // folded weights [c][o]
    __shared__ float sbe[CH_];
    __shared__ float sf[T_*CH_];     // f [t][o] / W1 stage
    __shared__ float red_s[128];
    __shared__ float red_q[128];
    __shared__ float sbf[C_];
    __shared__ unsigned s_last;

    int bid = blockIdx.x;
    int tid = threadIdx.x;

    if (bid & 1) {
        // ---- r path: r[b][t][hw] = Wr . x + br ----
        if (tid < 32) xg[tid] = Wr[tid];
        __syncthreads();
        int gt = (bid >> 1)*128 + tid;     // 131072 threads, 4 hw each
        int hw4 = gt & 1023;
        int bt  = gt >> 10;
        int b = bt >> 6, t = bt & 63;
        const float4* xp = (const float4*)(x + (size_t)(b*C_*T_ + t)*HW_) + hw4;
        float brv = br[0];
        float4 acc = make_float4(brv, brv, brv, brv);
        #pragma unroll
        for (int cc = 0; cc < 4; cc++) {
            float4 v[8];
            #pragma unroll
            for (int j = 0; j < 8; j++)
                v[j] = xp[(size_t)(cc*8+j)*T_*(HW_/4)];
            #pragma unroll
            for (int j = 0; j < 8; j++) {
                float wc = xg[cc*8+j];
                acc.x += wc*v[j].x; acc.y += wc*v[j].y;
                acc.z += wc*v[j].z; acc.w += wc*v[j].w;
            }
        }
        ((float4*)g_r)[gt] = acc;
        return;
    }

    // ---- gather path ----
    int bn = bid >> 1;                     // 0..1023
    int b = bn >> 9;
    int idx = coord[bn*2]*64 + coord[bn*2+1];

    // issue 16 scattered x loads early (max MLP)
    const float* xp = x + (size_t)b*C_*T_*HW_ + idx;
    float rv[16];
    #pragma unroll
    for (int i = 0; i < 16; i++)
        rv[i] = xp[(size_t)(tid + i*128) * HW_];

    // stage W1 -> sf, Wf -> xg, bf -> sbf
    for (int e = tid; e < CH_*C_; e += 128) sf[e] = W1[e];
    for (int e = tid; e < C_*C_; e += 128) xg[e] = Wf[e];
    if (tid < 32) sbf[tid] = bf[tid];
    __syncthreads();

    // fold: sWt[c][o] = sum_k W1[o][k] * Wf[k][c]
    #pragma unroll
    for (int i = 0; i < 4; i++) {
        int e = tid*4 + i;
        int c = e >> 4, o = e & 15;
        float a = 0.f;
        #pragma unroll
        for (int k = 0; k < 32; k++) a += sf[o*32+k] * xg[k*32 + c];
        sWt[c*CH_+o] = a;
    }
    if (tid < CH_) {
        float bb = b1[tid];
        #pragma unroll
        for (int k = 0; k < 32; k++) bb += sf[tid*32+k] * sbf[k];
        sbe[tid] = bb;
    }
    __syncthreads();
    #pragma unroll
    for (int i = 0; i < 16; i++) xg[tid + i*128] = rv[i];   // park x [c][t]
    __syncthreads();

    // f[t][o] = beff[o] + sum_c Wt[c][o] * xg[c][t]
    #pragma unroll
    for (int i = 0; i < 8; i++) {
        int e = tid + i*128;
        int t = e >> 4, o = e & 15;
        float a = sbe[o];
        #pragma unroll
        for (int c = 0; c < 32; c++) a += sWt[c*CH_+o] * xg[c*64+t];
        sf[e] = a;
    }
    __syncthreads();

    // store f -> g_f quad-plane layout: plane p = t*4+q, slot bn
    {
        float4* gf4 = (float4*)g_f;
        const float4* sf4 = (const float4*)sf;
        #pragma unroll
        for (int i = 0; i < 2; i++) {
            int e4 = tid + i*128;            // e4 = t*4 + q
            gf4[(size_t)e4*BN_ + bn] = sf4[e4];
        }
    }

    // table-based stats
    {
        int o = tid & 15, j = tid >> 4;
        float s_acc = 0.f, q_acc = 0.f;
        #pragma unroll
        for (int k = 0; k < 8; k++) {
            int i  = j + k*8;
            int i1 = (i < 63) ? i + 1 : 63;
            float fi  = sf[i*16 + o];
            float fi1 = sf[i1*16 + o];
            s_acc += c_tab.wl[i] * fi;
            q_acc += c_tab.A[i]*fi*fi + c_tab.Bc[i]*fi*fi1 + c_tab.Cc[i]*fi1*fi1;
        }
        red_s[j*16 + o] = s_acc;
        red_q[j*16 + o] = q_acc;
    }
    __syncthreads();
    if (tid < 32) {
        int c = tid & 15;
        const float* src = (tid < 16) ? red_s : red_q;
        float tot = 0.f;
        #pragma unroll
        for (int jj = 0; jj < 8; jj++) tot += src[jj*16 + c];
        g_part[tid*BN_ + bn] = tot;
    }

    // last gather block folds g_part -> g_ss
    __threadfence();
    if (tid == 0) s_last = (atomicAdd(&g_count, 1u) == 1023u) ? 1u : 0u;
    __syncthreads();
    if (s_last) {
        int c = tid >> 2, qd = tid & 3;
        const float4* p = (const float4*)(g_part + c*BN_) + qd*64;
        float acc = 0.f;
        #pragma unroll 16
        for (int k = 0; k < 64; k++) {
            float4 v4 = p[k];
            acc += (v4.x + v4.y) + (v4.z + v4.w);
        }
        red_s[tid] = acc;
        __syncthreads();
        if (tid < 32) {
            g_ss[tid] = (red_s[tid*4] + red_s[tid*4+1])
                      + (red_s[tid*4+2] + red_s[tid*4+3]);
            if (tid == 0) g_count = 0;   // reset for next graph replay
        }
    }
}

// ============================================================================
// k_fin: blocks [0,3200) -> result lerp; blocks [3200,4800) -> BN+ReLU+W2
// (byte-identical to the 65.2 champion)
// ============================================================================
__global__ void __launch_bounds__(256) k_fin(
    const float* __restrict__ gamma, const float* __restrict__ beta,
    const float* __restrict__ W2, const float* __restrict__ b2,
    float* __restrict__ out)
{
    __shared__ float sW2[CH_*CH_], sb2[CH_], ssc[CH_], ssh[CH_];

    if (blockIdx.x < 3200) {
        int tid = blockIdx.x*256 + threadIdx.x;      // 819200
        int hw4 = tid & 1023;
        int bt  = tid >> 10;
        int t = bt % FT_;
        int b = bt / FT_;
        const float step = (float)(63.0/399.0);
        float pos = (float)t * step;
        int i0 = (int)pos;
        int i1 = min(i0+1, T_-1);
        float w = pos - (float)i0, w0 = 1.f - w;
        float4 a = ((const float4*)(g_r + (b*T_+i0)*HW_))[hw4];
        float4 c = ((const float4*)(g_r + (b*T_+i1)*HW_))[hw4];
        float4 v = make_float4(a.x*w0 + c.x*w, a.y*w0 + c.y*w,
                               a.z*w0 + c.z*w, a.w*w0 + c.w*w);
        ((float4*)(out + OUT_OFF_RESULT))[tid] = v;
        return;
    }

    if (threadIdx.x < CH_*CH_) sW2[threadIdx.x] = W2[threadIdx.x];
    if (threadIdx.x < CH_) {
        int o = threadIdx.x;
        sb2[o] = b2[o];
        float mean = g_ss[o]    * (1.f/(float)CNT_);
        float var  = g_ss[o+16] * (1.f/(float)CNT_) - mean*mean;
        float sc = gamma[o] * rsqrtf(var + 1e-5f);
        ssc[o] = sc;
        ssh[o] = beta[o] - mean*sc;
    }
    __syncthreads();
    int tid = (blockIdx.x - 3200)*256 + threadIdx.x;  // 409600
    int b = tid / L_;
    int l = tid - b*L_;
    int t = l >> 9, n = l & (N_-1);
    int bn = b*N_ + n;
    const float step = (float)(63.0/399.0);
    float pos = (float)t * step;
    int i0 = (int)pos;
    int i1 = min(i0+1, T_-1);
    float w = pos - (float)i0, w0 = 1.f - w;
    const float4* gf4 = (const float4*)g_f;
    float4 a0 = gf4[(size_t)(i0*4+0)*BN_ + bn];
    float4 a1 = gf4[(size_t)(i0*4+1)*BN_ + bn];
    float4 a2 = gf4[(size_t)(i0*4+2)*BN_ + bn];
    float4 a3 = gf4[(size_t)(i0*4+3)*BN_ + bn];
    float4 c0 = gf4[(size_t)(i1*4+0)*BN_ + bn];
    float4 c1 = gf4[(size_t)(i1*4+1)*BN_ + bn];
    float4 c2 = gf4[(size_t)(i1*4+2)*BN_ + bn];
    float4 c3 = gf4[(size_t)(i1*4+3)*BN_ + bn];
    float hr[CH_];
    hr[0]=a0.x*w0+c0.x*w; hr[1]=a0.y*w0+c0.y*w; hr[2]=a0.z*w0+c0.z*w; hr[3]=a0.w*w0+c0.w*w;
    hr[4]=a1.x*w0+c1.x*w; hr[5]=a1.y*w0+c1.y*w; hr[6]=a1.z*w0+c1.z*w; hr[7]=a1.w*w0+c1.w*w;
    hr[8]=a2.x*w0+c2.x*w; hr[9]=a2.y*w0+c2.y*w; hr[10]=a2.z*w0+c2.z*w; hr[11]=a2.w*w0+c2.w*w;
    hr[12]=a3.x*w0+c3.x*w; hr[13]=a3.y*w0+c3.y*w; hr[14]=a3.z*w0+c3.z*w; hr[15]=a3.w*w0+c3.w*w;
    #pragma unroll
    for (int o = 0; o < CH_; o++) hr[o] = fmaxf(ssc[o]*hr[o] + ssh[o], 0.f);
    #pragma unroll
    for (int o2 = 0; o2 < CH_; o2++) {
        float acc = sb2[o2];
        #pragma unroll
        for (int o = 0; o < CH_; o++) acc += sW2[o2*16+o] * hr[o];
        out[((size_t)(b*CH_+o2))*L_ + l] = acc;
    }
}

extern "C" void kernel_launch(void* const* d_in, const int* in_sizes, int n_in,
                              void* d_out, int out_size) {
    const float* x     = (const float*)d_in[0];
    const int*   coord = (const int*)  d_in[1];
    const float* Wf    = (const float*)d_in[2];
    const float* bf    = (const float*)d_in[3];
    const float* Wr    = (const float*)d_in[4];
    const float* br    = (const float*)d_in[5];
    const float* W1    = (const float*)d_in[6];
    const float* b1    = (const float*)d_in[7];
    const float* gamma = (const float*)d_in[8];
    const float* beta  = (const float*)d_in[9];
    const float* W2    = (const float*)d_in[10];
    const float* b2    = (const float*)d_in[11];
    float* out = (float*)d_out;

    k_main<<<2048, 128>>>(x, coord, Wr, br, W1, Wf, b1, bf);
    k_fin <<<4800, 256>>>(gamma, beta, W2, b2, out);
}

// round 13
// speedup vs baseline: 1.3243x; 1.1006x over previous
#include <cuda_runtime.h>
#include <cstdint>

#define B_   2
#define C_   32
#define T_   64
#define HW_  4096
#define N_   512
#define BN_  (B_*N_)         /* 1024 */
#define CH_  16
#define FT_  400
#define L_   (FT_*N_)        /* 204800 */
#define CNT_ (B_*L_)         /* 409600 */
#define OUT_OFF_RESULT ((size_t)B_*CH_*L_)  /* 6,553,600 */

// ---- scratch (device globals) ----
__device__ __align__(16) float g_r[B_*T_*HW_];            // 2 MB
// g_f: quad-plane layout. float4 plane p = t*4 + q, index [p][bn]
__device__ __align__(16) float g_f[(size_t)T_*4*BN_*4];   // 4 MB
__device__ __align__(16) float g_part[32*BN_];            // [col][bn]
__device__ float g_ss[32];                                // sums[16] + sumsqs[16]
__device__ unsigned g_count = 0;

// ---- compile-time lerp stat tables (fp32 ops identical to reference) ----
struct LerpTab { float wl[64]; float A[64]; float Bc[64]; float Cc[64]; };
constexpr LerpTab make_tab() {
    LerpTab tb{};
    const float step = (float)(63.0/399.0);
    for (int t = 0; t < FT_; t++) {
        float pos = (float)t * step;
        int i0 = (int)pos;
        int i1 = (i0 + 1 < T_) ? i0 + 1 : T_ - 1;
        float w = pos - (float)i0;
        float w0 = 1.0f - w;
        if (i1 == i0) {
            tb.wl[i0] += (w0 + w);
            tb.A[i0]  += (w0 + w) * (w0 + w);
        } else {
            tb.wl[i0] += w0;  tb.wl[i1] += w;
            tb.A[i0]  += w0 * w0;
            tb.Bc[i0] += 2.0f * w0 * w;
            tb.Cc[i0] += w * w;
        }
    }
    return tb;
}
__constant__ LerpTab c_tab = make_tab();

// ============================================================================
// k_main: blocks [0,1024) gather path; blocks [1024,2048) r path.
// BYTE-IDENTICAL to the round-7 champion (41.9 us measured).
// ============================================================================
__global__ void __launch_bounds__(128, 8) k_main(
    const float* __restrict__ x, const int* __restrict__ coord,
    const float* __restrict__ Wr, const float* __restrict__ br,
    const float* __restrict__ W1, const float* __restrict__ Wf,
    const float* __restrict__ b1, const float* __restrict__ bf)
{
    __shared__ float xg[C_*T_];      // gather x [c][t] / Wf stage / r: Wr
    __shared__ float sWt[C_*CH_];    // folded weights [c][o]
    __shared__ float sbe[CH_];
    __shared__ float sf[T_*CH_];     // f [t][o] / W1 stage
    __shared__ float red_s[128];
    __shared__ float red_q[128];
    __shared__ float sbf[C_];
    __shared__ unsigned s_last;

    int bid = blockIdx.x;
    int tid = threadIdx.x;

    if (bid >= 1024) {
        // ---- r path: r[b][t][hw] = Wr . x + br ----
        if (tid < 32) xg[tid] = Wr[tid];
        __syncthreads();
        int gt = (bid - 1024)*128 + tid;   // 131072 threads, 4 hw each
        int hw4 = gt & 1023;
        int bt  = gt >> 10;
        int b = bt >> 6, t = bt & 63;
        const float4* xp = (const float4*)(x + (size_t)(b*C_*T_ + t)*HW_) + hw4;
        float brv = br[0];
        float4 acc = make_float4(brv, brv, brv, brv);
        #pragma unroll
        for (int cc = 0; cc < 4; cc++) {
            float4 v[8];
            #pragma unroll
            for (int j = 0; j < 8; j++)
                v[j] = xp[(size_t)(cc*8+j)*T_*(HW_/4)];
            #pragma unroll
            for (int j = 0; j < 8; j++) {
                float wc = xg[cc*8+j];
                acc.x += wc*v[j].x; acc.y += wc*v[j].y;
                acc.z += wc*v[j].z; acc.w += wc*v[j].w;
            }
        }
        ((float4*)g_r)[gt] = acc;
        return;
    }

    // ---- gather path ----
    int bn = bid;                          // 0..1023
    int b = bn >> 9;
    int idx = coord[bn*2]*64 + coord[bn*2+1];

    const float* xp = x + (size_t)b*C_*T_*HW_ + idx;
    float rv[16];
    #pragma unroll
    for (int i = 0; i < 16; i++)
        rv[i] = xp[(size_t)(tid + i*128) * HW_];

    for (int e = tid; e < CH_*C_; e += 128) sf[e] = W1[e];
    for (int e = tid; e < C_*C_; e += 128) xg[e] = Wf[e];
    if (tid < 32) sbf[tid] = bf[tid];
    __syncthreads();

    #pragma unroll
    for (int i = 0; i < 4; i++) {
        int e = tid*4 + i;
        int c = e >> 4, o = e & 15;
        float a = 0.f;
        #pragma unroll
        for (int k = 0; k < 32; k++) a += sf[o*32+k] * xg[k*32 + c];
        sWt[c*CH_+o] = a;
    }
    if (tid < CH_) {
        float bb = b1[tid];
        #pragma unroll
        for (int k = 0; k < 32; k++) bb += sf[tid*32+k] * sbf[k];
        sbe[tid] = bb;
    }
    __syncthreads();
    #pragma unroll
    for (int i = 0; i < 16; i++) xg[tid + i*128] = rv[i];
    __syncthreads();

    #pragma unroll
    for (int i = 0; i < 8; i++) {
        int e = tid + i*128;
        int t = e >> 4, o = e & 15;
        float a = sbe[o];
        #pragma unroll
        for (int c = 0; c < 32; c++) a += sWt[c*CH_+o] * xg[c*64+t];
        sf[e] = a;
    }
    __syncthreads();

    {
        float4* gf4 = (float4*)g_f;
        const float4* sf4 = (const float4*)sf;
        #pragma unroll
        for (int i = 0; i < 2; i++) {
            int e4 = tid + i*128;            // e4 = t*4 + q
            gf4[(size_t)e4*BN_ + bn] = sf4[e4];
        }
    }

    {
        int o = tid & 15, j = tid >> 4;
        float s_acc = 0.f, q_acc = 0.f;
        #pragma unroll
        for (int k = 0; k < 8; k++) {
            int i  = j + k*8;
            int i1 = (i < 63) ? i + 1 : 63;
            float fi  = sf[i*16 + o];
            float fi1 = sf[i1*16 + o];
            s_acc += c_tab.wl[i] * fi;
            q_acc += c_tab.A[i]*fi*fi + c_tab.Bc[i]*fi*fi1 + c_tab.Cc[i]*fi1*fi1;
        }
        red_s[j*16 + o] = s_acc;
        red_q[j*16 + o] = q_acc;
    }
    __syncthreads();
    if (tid < 32) {
        int c = tid & 15;
        const float* src = (tid < 16) ? red_s : red_q;
        float tot = 0.f;
        #pragma unroll
        for (int jj = 0; jj < 8; jj++) tot += src[jj*16 + c];
        g_part[tid*BN_ + bn] = tot;
    }

    __threadfence();
    if (tid == 0) s_last = (atomicAdd(&g_count, 1u) == 1023u) ? 1u : 0u;
    __syncthreads();
    if (s_last) {
        int c = tid >> 2, qd = tid & 3;
        const float4* p = (const float4*)(g_part + c*BN_) + qd*64;
        float acc = 0.f;
        #pragma unroll 16
        for (int k = 0; k < 64; k++) {
            float4 v4 = p[k];
            acc += (v4.x + v4.y) + (v4.z + v4.w);
        }
        red_s[tid] = acc;
        __syncthreads();
        if (tid < 32) {
            g_ss[tid] = (red_s[tid*4] + red_s[tid*4+1])
                      + (red_s[tid*4+2] + red_s[tid*4+3]);
            if (tid == 0) g_count = 0;   // reset for next graph replay
        }
    }
}

// ============================================================================
// k_fin: blocks [0,800) -> 4-cell BN+ReLU+W2 epilogue (128 thr, 4 n per thr);
//        blocks [800,4000) -> result lerp (128 thr, 2 float4 per thr).
// ============================================================================
__global__ void __launch_bounds__(128) k_fin(
    const float* __restrict__ gamma, const float* __restrict__ beta,
    const float* __restrict__ W2, const float* __restrict__ b2,
    float* __restrict__ out)
{
    __shared__ float4 sW2[64];
    __shared__ float sb2[CH_], ssc[CH_], ssh[CH_];

    int bid = blockIdx.x;
    int tid = threadIdx.x;

    if (bid >= 800) {
        // ---- result = lerp_t(r) : 3200 blocks x 128 thr x 2 float4 ----
        int base = (bid - 800)*128 + tid;            // 0..409599
        #pragma unroll
        for (int h = 0; h < 2; h++) {
            int e = base + h*409600;
            int hw4 = e & 1023;
            int bt  = e >> 10;
            int t = bt % FT_;
            int b = bt / FT_;
            const float step = (float)(63.0/399.0);
            float pos = (float)t * step;
            int i0 = (int)pos;
            int i1 = min(i0+1, T_-1);
            float w = pos - (float)i0, w0 = 1.f - w;
            float4 a = ((const float4*)(g_r + (b*T_+i0)*HW_))[hw4];
            float4 c = ((const float4*)(g_r + (b*T_+i1)*HW_))[hw4];
            float4 v = make_float4(a.x*w0 + c.x*w, a.y*w0 + c.y*w,
                                   a.z*w0 + c.z*w, a.w*w0 + c.w*w);
            ((float4*)(out + OUT_OFF_RESULT))[e] = v;
        }
        return;
    }

    // ---- epilogue: 800 blocks x 128 thr, 4 consecutive n per thread ----
    if (tid < 64) sW2[tid] = ((const float4*)W2)[tid];
    if (tid < CH_) {
        int o = tid;
        sb2[o] = b2[o];
        float mean = g_ss[o]    * (1.f/(float)CNT_);
        float var  = g_ss[o+16] * (1.f/(float)CNT_) - mean*mean;
        float sc = gamma[o] * rsqrtf(var + 1e-5f);
        ssc[o] = sc;
        ssh[o] = beta[o] - mean*sc;
    }
    __syncthreads();

    int e = bid*128 + tid;               // 0..102399 (cell groups of 4)
    int b = e / (L_/4);                  // L_/4 = 51200
    int l = (e - b*(L_/4)) * 4;          // multiple of 4
    int t = l >> 9, n = l & (N_-1);      // 4 cells: n..n+3, same t
    int bn = b*N_ + n;
    const float step = (float)(63.0/399.0);
    float pos = (float)t * step;
    int i0 = (int)pos;
    int i1 = min(i0+1, T_-1);
    float w = pos - (float)i0, w0 = 1.f - w;

    const float4* gf4 = (const float4*)g_f;
    float hr[4][CH_];
    #pragma unroll
    for (int q = 0; q < 4; q++) {
        size_t pa = (size_t)(i0*4+q)*BN_ + bn;
        size_t pc = (size_t)(i1*4+q)*BN_ + bn;
        float sc0 = ssc[q*4+0], sc1 = ssc[q*4+1], sc2 = ssc[q*4+2], sc3 = ssc[q*4+3];
        float sh0 = ssh[q*4+0], sh1 = ssh[q*4+1], sh2 = ssh[q*4+2], sh3 = ssh[q*4+3];
        #pragma unroll
        for (int j = 0; j < 4; j++) {
            float4 av = gf4[pa + j];
            float4 cv = gf4[pc + j];
            hr[j][q*4+0] = fmaxf(sc0*(av.x*w0 + cv.x*w) + sh0, 0.f);
            hr[j][q*4+1] = fmaxf(sc1*(av.y*w0 + cv.y*w) + sh1, 0.f);
            hr[j][q*4+2] = fmaxf(sc2*(av.z*w0 + cv.z*w) + sh2, 0.f);
            hr[j][q*4+3] = fmaxf(sc3*(av.w*w0 + cv.w*w) + sh3, 0.f);
        }
    }

    float* outp = out + (size_t)b*CH_*L_ + l;
    #pragma unroll
    for (int o2 = 0; o2 < CH_; o2++) {
        float4 wa = sW2[o2*4+0], wb = sW2[o2*4+1], wc = sW2[o2*4+2], wd = sW2[o2*4+3];
        float bb = sb2[o2];
        float r[4];
        #pragma unroll
        for (int j = 0; j < 4; j++) {
            float acc = bb;
            acc += wa.x*hr[j][0];  acc += wa.y*hr[j][1];
            acc += wa.z*hr[j][2];  acc += wa.w*hr[j][3];
            acc += wb.x*hr[j][4];  acc += wb.y*hr[j][5];
            acc += wb.z*hr[j][6];  acc += wb.w*hr[j][7];
            acc += wc.x*hr[j][8];  acc += wc.y*hr[j][9];
            acc += wc.z*hr[j][10]; acc += wc.w*hr[j][11];
            acc += wd.x*hr[j][12]; acc += wd.y*hr[j][13];
            acc += wd.z*hr[j][14]; acc += wd.w*hr[j][15];
            r[j] = acc;
        }
        *(float4*)(outp + (size_t)o2*L_) = make_float4(r[0], r[1], r[2], r[3]);
    }
}

extern "C" void kernel_launch(void* const* d_in, const int* in_sizes, int n_in,
                              void* d_out, int out_size) {
    const float* x     = (const float*)d_in[0];
    const int*   coord = (const int*)  d_in[1];
    const float* Wf    = (const float*)d_in[2];
    const float* bf    = (const float*)d_in[3];
    const float* Wr    = (const float*)d_in[4];
    const float* br    = (const float*)d_in[5];
    const float* W1    = (const float*)d_in[6];
    const float* b1    = (const float*)d_in[7];
    const float* gamma = (const float*)d_in[8];
    const float* beta  = (const float*)d_in[9];
    const float* W2    = (const float*)d_in[10];
    const float* b2    = (const float*)d_in[11];
    float* out = (float*)d_out;

    k_main<<<2048, 128>>>(x, coord, Wr, br, W1, Wf, b1, bf);
    k_fin <<<4000, 128>>>(gamma, beta, W2, b2, out);
}

// round 15
// speedup vs baseline: 1.3625x; 1.0288x over previous
#include <cuda_runtime.h>
#include <cstdint>

#define B_   2
#define C_   32
#define T_   64
#define HW_  4096
#define N_   512
#define BN_  (B_*N_)         /* 1024 */
#define CH_  16
#define FT_  400
#define L_   (FT_*N_)        /* 204800 */
#define CNT_ (B_*L_)         /* 409600 */
#define OUT_OFF_RESULT ((size_t)B_*CH_*L_)  /* 6,553,600 */

// ---- scratch (device globals) ----
__device__ __align__(16) float g_r[B_*T_*HW_];            // 2 MB
// g_f: quad-plane layout. float4 plane p = t*4 + q, index [p][bn]
__device__ __align__(16) float g_f[(size_t)T_*4*BN_*4];   // 4 MB
__device__ __align__(16) float g_part[32*BN_];            // [col][bn]
__device__ float g_ss[32];                                // sums[16] + sumsqs[16]
__device__ unsigned g_count = 0;

// ---- compile-time lerp stat tables (fp32 ops identical to reference) ----
struct LerpTab { float wl[64]; float A[64]; float Bc[64]; float Cc[64]; };
constexpr LerpTab make_tab() {
    LerpTab tb{};
    const float step = (float)(63.0/399.0);
    for (int t = 0; t < FT_; t++) {
        float pos = (float)t * step;
        int i0 = (int)pos;
        int i1 = (i0 + 1 < T_) ? i0 + 1 : T_ - 1;
        float w = pos - (float)i0;
        float w0 = 1.0f - w;
        if (i1 == i0) {
            tb.wl[i0] += (w0 + w);
            tb.A[i0]  += (w0 + w) * (w0 + w);
        } else {
            tb.wl[i0] += w0;  tb.wl[i1] += w;
            tb.A[i0]  += w0 * w0;
            tb.Bc[i0] += 2.0f * w0 * w;
            tb.Cc[i0] += w * w;
        }
    }
    return tb;
}
__constant__ LerpTab c_tab = make_tab();

// ============================================================================
// k_main: blocks [0,1024) gather path; blocks [1024,2048) r path.
// BYTE-IDENTICAL to the validated champion (41.9 us measured).
// ============================================================================
__global__ void __launch_bounds__(128, 8) k_main(
    const float* __restrict__ x, const int* __restrict__ coord,
    const float* __restrict__ Wr, const float* __restrict__ br,
    const float* __restrict__ W1, const float* __restrict__ Wf,
    const float* __restrict__ b1, const float* __restrict__ bf)
{
    __shared__ float xg[C_*T_];      // gather x [c][t] / Wf stage / r: Wr
    __shared__ float sWt[C_*CH_];    // folded weights [c][o]
    __shared__ float sbe[CH_];
    __shared__ float sf[T_*CH_];     // f [t][o] / W1 stage
    __shared__ float red_s[128];
    __shared__ float red_q[128];
    __shared__ float sbf[C_];
    __shared__ unsigned s_last;

    int bid = blockIdx.x;
    int tid = threadIdx.x;

    if (bid >= 1024) {
        // ---- r path: r[b][t][hw] = Wr . x + br ----
        if (tid < 32) xg[tid] = Wr[tid];
        __syncthreads();
        int gt = (bid - 1024)*128 + tid;   // 131072 threads, 4 hw each
        int hw4 = gt & 1023;
        int bt  = gt >> 10;
        int b = bt >> 6, t = bt & 63;
        const float4* xp = (const float4*)(x + (size_t)(b*C_*T_ + t)*HW_) + hw4;
        float brv = br[0];
        float4 acc = make_float4(brv, brv, brv, brv);
        #pragma unroll
        for (int cc = 0; cc < 4; cc++) {
            float4 v[8];
            #pragma unroll
            for (int j = 0; j < 8; j++)
                v[j] = xp[(size_t)(cc*8+j)*T_*(HW_/4)];
            #pragma unroll
            for (int j = 0; j < 8; j++) {
                float wc = xg[cc*8+j];
                acc.x += wc*v[j].x; acc.y += wc*v[j].y;
                acc.z += wc*v[j].z; acc.w += wc*v[j].w;
            }
        }
        ((float4*)g_r)[gt] = acc;
        return;
    }

    // ---- gather path ----
    int bn = bid;                          // 0..1023
    int b = bn >> 9;
    int idx = coord[bn*2]*64 + coord[bn*2+1];

    const float* xp = x + (size_t)b*C_*T_*HW_ + idx;
    float rv[16];
    #pragma unroll
    for (int i = 0; i < 16; i++)
        rv[i] = xp[(size_t)(tid + i*128) * HW_];

    for (int e = tid; e < CH_*C_; e += 128) sf[e] = W1[e];
    for (int e = tid; e < C_*C_; e += 128) xg[e] = Wf[e];
    if (tid < 32) sbf[tid] = bf[tid];
    __syncthreads();

    #pragma unroll
    for (int i = 0; i < 4; i++) {
        int e = tid*4 + i;
        int c = e >> 4, o = e & 15;
        float a = 0.f;
        #pragma unroll
        for (int k = 0; k < 32; k++) a += sf[o*32+k] * xg[k*32 + c];
        sWt[c*CH_+o] = a;
    }
    if (tid < CH_) {
        float bb = b1[tid];
        #pragma unroll
        for (int k = 0; k < 32; k++) bb += sf[tid*32+k] * sbf[k];
        sbe[tid] = bb;
    }
    __syncthreads();
    #pragma unroll
    for (int i = 0; i < 16; i++) xg[tid + i*128] = rv[i];
    __syncthreads();

    #pragma unroll
    for (int i = 0; i < 8; i++) {
        int e = tid + i*128;
        int t = e >> 4, o = e & 15;
        float a = sbe[o];
        #pragma unroll
        for (int c = 0; c < 32; c++) a += sWt[c*CH_+o] * xg[c*64+t];
        sf[e] = a;
    }
    __syncthreads();

    {
        float4* gf4 = (float4*)g_f;
        const float4* sf4 = (const float4*)sf;
        #pragma unroll
        for (int i = 0; i < 2; i++) {
            int e4 = tid + i*128;            // e4 = t*4 + q
            gf4[(size_t)e4*BN_ + bn] = sf4[e4];
        }
    }

    {
        int o = tid & 15, j = tid >> 4;
        float s_acc = 0.f, q_acc = 0.f;
        #pragma unroll
        for (int k = 0; k < 8; k++) {
            int i  = j + k*8;
            int i1 = (i < 63) ? i + 1 : 63;
            float fi  = sf[i*16 + o];
            float fi1 = sf[i1*16 + o];
            s_acc += c_tab.wl[i] * fi;
            q_acc += c_tab.A[i]*fi*fi + c_tab.Bc[i]*fi*fi1 + c_tab.Cc[i]*fi1*fi1;
        }
        red_s[j*16 + o] = s_acc;
        red_q[j*16 + o] = q_acc;
    }
    __syncthreads();
    if (tid < 32) {
        int c = tid & 15;
        const float* src = (tid < 16) ? red_s : red_q;
        float tot = 0.f;
        #pragma unroll
        for (int jj = 0; jj < 8; jj++) tot += src[jj*16 + c];
        g_part[tid*BN_ + bn] = tot;
    }

    __threadfence();
    if (tid == 0) s_last = (atomicAdd(&g_count, 1u) == 1023u) ? 1u : 0u;
    __syncthreads();
    if (s_last) {
        int c = tid >> 2, qd = tid & 3;
        const float4* p = (const float4*)(g_part + c*BN_) + qd*64;
        float acc = 0.f;
        #pragma unroll 16
        for (int k = 0; k < 64; k++) {
            float4 v4 = p[k];
            acc += (v4.x + v4.y) + (v4.z + v4.w);
        }
        red_s[tid] = acc;
        __syncthreads();
        if (tid < 32) {
            g_ss[tid] = (red_s[tid*4] + red_s[tid*4+1])
                      + (red_s[tid*4+2] + red_s[tid*4+3]);
            if (tid == 0) g_count = 0;   // reset for next graph replay
        }
    }
}

// ============================================================================
// k_fin: blocks [0,1600) -> 2-cell BN+ReLU+W2 epilogue (128 thr; cells tid and
//        tid+128 of a 256-cell slab -> all load/store warps fully coalesced);
//        blocks [1600,4800) -> result lerp (128 thr, 2 float4 per thr).
// ============================================================================
__global__ void __launch_bounds__(128) k_fin(
    const float* __restrict__ gamma, const float* __restrict__ beta,
    const float* __restrict__ W2, const float* __restrict__ b2,
    float* __restrict__ out)
{
    __shared__ float4 sW2[64];
    __shared__ float sb2[CH_], ssc[CH_], ssh[CH_];

    int bid = blockIdx.x;
    int tid = threadIdx.x;

    if (bid >= 1600) {
        // ---- result = lerp_t(r) : 3200 blocks x 128 thr x 2 float4 ----
        int base = (bid - 1600)*128 + tid;           // 0..409599
        #pragma unroll
        for (int h = 0; h < 2; h++) {
            int e = base + h*409600;
            int hw4 = e & 1023;
            int bt  = e >> 10;
            int t = bt % FT_;
            int b = bt / FT_;
            const float step = (float)(63.0/399.0);
            float pos = (float)t * step;
            int i0 = (int)pos;
            int i1 = min(i0+1, T_-1);
            float w = pos - (float)i0, w0 = 1.f - w;
            float4 a = ((const float4*)(g_r + (b*T_+i0)*HW_))[hw4];
            float4 c = ((const float4*)(g_r + (b*T_+i1)*HW_))[hw4];
            float4 v = make_float4(a.x*w0 + c.x*w, a.y*w0 + c.y*w,
                                   a.z*w0 + c.z*w, a.w*w0 + c.w*w);
            ((float4*)(out + OUT_OFF_RESULT))[e] = v;
        }
        return;
    }

    // ---- epilogue: 1600 blocks x 128 thr x 2 cells (256-cell slab) ----
    if (tid < 64) sW2[tid] = ((const float4*)W2)[tid];
    if (tid < CH_) {
        int o = tid;
        sb2[o] = b2[o];
        float mean = g_ss[o]    * (1.f/(float)CNT_);
        float var  = g_ss[o+16] * (1.f/(float)CNT_) - mean*mean;
        float sc = gamma[o] * rsqrtf(var + 1e-5f);
        ssc[o] = sc;
        ssh[o] = beta[o] - mean*sc;
    }
    __syncthreads();

    // slab: 800 blocks per batch, 256 cells per block (half a t-row)
    int b = (bid >= 800) ? 1 : 0;
    int slab = bid - b*800;                // 0..799
    int l0 = slab * 256;                   // slab base within batch
    int t = l0 >> 9;
    int n0 = l0 & (N_-1);                  // 0 or 256
    const float step = (float)(63.0/399.0);
    float pos = (float)t * step;
    int i0 = (int)pos;
    int i1 = min(i0+1, T_-1);
    float w = pos - (float)i0, w0 = 1.f - w;

    const float4* gf4 = (const float4*)g_f;
    float hr[2][CH_];
    #pragma unroll
    for (int j = 0; j < 2; j++) {          // cell j: n = n0 + tid + j*128
        int bn = b*N_ + n0 + tid + j*128;
        #pragma unroll
        for (int q = 0; q < 4; q++) {
            float4 av = gf4[(size_t)(i0*4+q)*BN_ + bn];
            float4 cv = gf4[(size_t)(i1*4+q)*BN_ + bn];
            hr[j][q*4+0] = fmaxf(ssc[q*4+0]*(av.x*w0 + cv.x*w) + ssh[q*4+0], 0.f);
            hr[j][q*4+1] = fmaxf(ssc[q*4+1]*(av.y*w0 + cv.y*w) + ssh[q*4+1], 0.f);
            hr[j][q*4+2] = fmaxf(ssc[q*4+2]*(av.z*w0 + cv.z*w) + ssh[q*4+2], 0.f);
            hr[j][q*4+3] = fmaxf(ssc[q*4+3]*(av.w*w0 + cv.w*w) + ssh[q*4+3], 0.f);
        }
    }

    float* outp = out + (size_t)b*CH_*L_ + (size_t)t*N_ + n0 + tid;
    #pragma unroll
    for (int o2 = 0; o2 < CH_; o2++) {
        float4 wa = sW2[o2*4+0], wb = sW2[o2*4+1], wc = sW2[o2*4+2], wd = sW2[o2*4+3];
        float bb = sb2[o2];
        #pragma unroll
        for (int j = 0; j < 2; j++) {
            float acc = bb;
            acc += wa.x*hr[j][0];  acc += wa.y*hr[j][1];
            acc += wa.z*hr[j][2];  acc += wa.w*hr[j][3];
            acc += wb.x*hr[j][4];  acc += wb.y*hr[j][5];
            acc += wb.z*hr[j][6];  acc += wb.w*hr[j][7];
            acc += wc.x*hr[j][8];  acc += wc.y*hr[j][9];
            acc += wc.z*hr[j][10]; acc += wc.w*hr[j][11];
            acc += wd.x*hr[j][12]; acc += wd.y*hr[j][13];
            acc += wd.z*hr[j][14]; acc += wd.w*hr[j][15];
            outp[(size_t)o2*L_ + j*128] = acc;
        }
    }
}

extern "C" void kernel_launch(void* const* d_in, const int* in_sizes, int n_in,
                              void* d_out, int out_size) {
    const float* x     = (const float*)d_in[0];
    const int*   coord = (const int*)  d_in[1];
    const float* Wf    = (const float*)d_in[2];
    const float* bf    = (const float*)d_in[3];
    const float* Wr    = (const float*)d_in[4];
    const float* br    = (const float*)d_in[5];
    const float* W1    = (const float*)d_in[6];
    const float* b1    = (const float*)d_in[7];
    const float* gamma = (const float*)d_in[8];
    const float* beta  = (const float*)d_in[9];
    const float* W2    = (const float*)d_in[10];
    const float* b2    = (const float*)d_in[11];
    float* out = (float*)d_out;

    k_main<<<2048, 128>>>(x, coord, Wr, br, W1, Wf, b1, bf);
    k_fin <<<4800, 128>>>(gamma, beta, W2, b2, out);
}